// round 14
// baseline (speedup 1.0000x reference)
#include <cuda_runtime.h>
#include <cuda_fp16.h>
#include <math.h>
#include <stdint.h>

#define NNODE   512
#define KPAD    208
#define ROWS_ENC (128*512)   // 65536
#define ROWS_DEC (64*512)    // 32768
#define BSTRIDE  (512*KPAD)
#define INV_S2  0.70710678118654752440f

// ---------------- scratch (device globals; no allocation) ----------------
__device__ __align__(16) __half g_MMh[1024*512];      // [M1;M2] fp16, K contiguous
__device__ __align__(16) float  g_P[512*512];
__device__ float g_rs[512];
__device__ __align__(16) __half g_CATh[ROWS_ENC*KPAD]; // row-major: comb(68)|Q1(68)|Q2(68)|pad0
__device__ __align__(16) __half g_CATt[ROWS_ENC*68];   // comb, K-contig: [(bp*68+c)*512 + v]
__device__ __align__(16) float g_H[ROWS_ENC*64];
__device__ __align__(16) float g_Hdec[ROWS_DEC*64];
__device__ __align__(16) float g_z[ROWS_ENC*64];
__device__ __align__(16) float g_xt_enc[6*ROWS_ENC*4];
__device__ __align__(16) float g_xt_dec[ROWS_DEC*4];
__device__ float g_tod[64*12];
__device__ __align__(16) __half g_Wzrh[3][KPAD*128];  // [k][g], rows 204..207 zero
__device__ float g_bzr[3][128];
__device__ __align__(16) __half g_Wch[3][KPAD*64];    // [k][c]
__device__ float g_bc[3][64];
__device__ __align__(16) float g_Wmix[128*64];
__device__ float g_bmix[64];

// ---------------- helpers ----------------
__device__ __forceinline__ void mma_f16(float* d, const uint32_t* a, const uint32_t* b) {
    asm volatile(
        "mma.sync.aligned.m16n8k16.row.col.f32.f16.f16.f32 "
        "{%0,%1,%2,%3}, {%4,%5,%6,%7}, {%8,%9}, {%0,%1,%2,%3};"
        : "+f"(d[0]), "+f"(d[1]), "+f"(d[2]), "+f"(d[3])
        : "r"(a[0]), "r"(a[1]), "r"(a[2]), "r"(a[3]), "r"(b[0]), "r"(b[1]));
}
__device__ __forceinline__ float sigm(float x) { return 1.f / (1.f + __expf(-x)); }
__device__ __forceinline__ uint32_t s2u(const void* p) {
    return (uint32_t)__cvta_generic_to_shared(p);
}
__device__ __forceinline__ void ldsm4(uint32_t* r, uint32_t a) {
    asm volatile("ldmatrix.sync.aligned.m8n8.x4.shared.b16 {%0,%1,%2,%3}, [%4];"
        : "=r"(r[0]), "=r"(r[1]), "=r"(r[2]), "=r"(r[3]) : "r"(a));
}

// ---------------- prep ----------------
__global__ void k_rowsum(const float* __restrict__ A) {
    int v = blockIdx.x;
    float s = 0.f;
    for (int w = threadIdx.x; w < 512; w += 128) s += A[v*512+w];
    __shared__ float sh[128];
    sh[threadIdx.x] = s; __syncthreads();
    for (int o = 64; o > 0; o >>= 1) {
        if (threadIdx.x < o) sh[threadIdx.x] += sh[threadIdx.x+o];
        __syncthreads();
    }
    if (threadIdx.x == 0) g_rs[v] = sh[0] + 1.0f;
}

__global__ void k_P(const float* __restrict__ A) {
    int idx = blockIdx.x*blockDim.x + threadIdx.x;
    if (idx >= 512*512) return;
    int w = idx >> 9, v = idx & 511;
    float a  = A[v*512+w];
    float an = (a + (v==w ? 1.f : 0.f)) / g_rs[v];
    float p  = 0.95f*an + 0.95f*a;
    g_P[w*512+v]   = p;
    g_MMh[w*512+v] = __float2half_rn((v==w ? 0.05f : 0.f) + p);   // M1
}

__global__ void k_M2() {
    int idx = blockIdx.x*blockDim.x + threadIdx.x;
    if (idx >= 512*512) return;
    int w = idx >> 9, v = idx & 511;
    const float* pw = g_P + w*512;
    float s = 0.f;
    #pragma unroll 8
    for (int u = 0; u < 512; u++) s += pw[u] * g_P[u*512+v];
    g_MMh[(512+w)*512+v] = __float2half_rn((w==v ? 0.05f : 0.f) + 0.05f*g_P[w*512+v] + s); // M2
}

__global__ void k_weights(const float* __restrict__ Wg, const float* __restrict__ bg) {
    int idx = blockIdx.x*blockDim.x + threadIdx.x;
    const int TZR = 3*204*128, TC = 3*204*64;
    if (idx < TZR) {
        int p = idx / (204*128); int rem = idx % (204*128);
        int k = rem / 128, g = rem % 128;
        int gate = (g < 64) ? 0 : 2;  int c = g & 63;
        int w1 = 6*p + gate;
        g_Wzrh[p][k*128+g] = __float2half_rn(Wg[(w1*204+k)*64+c] + Wg[((w1+1)*204+k)*64+c]);
    } else if (idx < TZR + TC) {
        int j = idx - TZR;
        int p = j / (204*64); int rem = j % (204*64);
        int k = rem / 64, c = rem % 64;
        int w1 = 6*p + 4;
        g_Wch[p][k*64+c] = __float2half_rn(Wg[(w1*204+k)*64+c] + Wg[((w1+1)*204+k)*64+c]);
    } else if (idx < TZR + TC + 3*128) {
        int j = idx - TZR - TC;
        int p = j / 128, g = j % 128;
        int gate = (g < 64) ? 0 : 2; int c = g & 63;
        g_bzr[p][g] = bg[(6*p+gate)*64+c] + bg[(6*p+gate+1)*64+c];
    } else if (idx < TZR + TC + 3*128 + 3*64) {
        int j = idx - TZR - TC - 3*128;
        int p = j / 64, c = j % 64;
        g_bc[p][c] = bg[(6*p+4)*64+c] + bg[(6*p+5)*64+c];
    }
}

__global__ void k_mixw(const float* __restrict__ Wi, const float* __restrict__ bi,
                       const float* __restrict__ Wm, const float* __restrict__ bm) {
    int idx = blockIdx.x*blockDim.x + threadIdx.x;
    if (idx < 4096) {
        int k = idx >> 6, c = idx & 63;
        float s = 0.f;
        for (int j = 0; j < 64; j++) {
            s += Wi[k*64+j]        * Wm[(256+2*j  )*64+c]
               + Wi[4096 + k*64+j] * Wm[(256+2*j+1)*64+c];
        }
        g_Wmix[k*64+c]      = 0.3f*s + 0.7f*Wm[(128+k)*64+c];
        g_Wmix[(64+k)*64+c] = 0.3f*s + 0.7f*Wm[(128+64+k)*64+c];
    } else if (idx < 4096 + 64) {
        int c = idx - 4096;
        float s = 0.f;
        for (int j = 0; j < 64; j++)
            s += 2.f*bi[j]    * Wm[(256+2*j  )*64+c]
               + 2.f*bi[64+j] * Wm[(256+2*j+1)*64+c];
        g_bmix[c] = 0.3f*(s + bm[128+c]) + 0.7f*bm[64+c];
    }
}

__global__ void k_tod(const float* __restrict__ st) {
    int idx = blockIdx.x*blockDim.x + threadIdx.x;
    if (idx >= 64*12) return;
    int b = idx / 12, t = idx % 12;
    g_tod[idx] = (float)(int)((st[(b*5+2)*12+t] + 0.5f) * 6.0f);
}

__global__ void k_xt_enc(const float* __restrict__ x, const float* __restrict__ st) {
    int idx = blockIdx.x*blockDim.x + threadIdx.x;
    if (idx >= 6*ROWS_ENC*4) return;
    int c   = idx & 3;
    int rem = idx >> 2;
    int row = rem & (ROWS_ENC-1);
    int t   = rem >> 16;
    int bp = row >> 9, n = row & 511;
    int b = bp & 63;
    float val;
    if (c < 3) {
        float xe = x[((b*3+c)*512+n)*12 + 2*t];
        float xo = x[((b*3+c)*512+n)*12 + 2*t + 1];
        val = ((bp < 64) ? (xe - xo) : (xe + xo)) * INV_S2;
    } else {
        int s = 2*t;
        float hour   = (st[(b*5+3)*12+s] + 0.5f) * 23.0f;
        float minute = (st[(b*5+4)*12+s] + 0.5f) * 59.0f;
        val = (float)(int)((hour*60.0f + minute) / 5.0f);
    }
    g_xt_enc[idx] = val;
}

// init: H=0, CATh/CATt comb for enc t=0 = [xt_enc(0) | 0], xt_dec init
__global__ void k_init_state() {
    int idx = blockIdx.x*blockDim.x + threadIdx.x;
    if (idx < ROWS_ENC*68) {
        int row = idx / 68, c = idx - row*68;
        int bp = row >> 9, n = row & 511;
        __half v;
        if (c < 4) {
            v = __float2half_rn(g_xt_enc[row*4 + c]);
        } else {
            v = __float2half_rn(0.f);
            g_H[(size_t)row*64 + (c-4)] = 0.f;
        }
        g_CATh[(size_t)row*KPAD + c] = v;
        g_CATt[((size_t)bp*68 + c)*512 + n] = v;
        return;
    }
    int j = idx - ROWS_ENC*68;
    if (j < ROWS_DEC*4) {
        int c = j & 3; int row = j >> 2; int b = row >> 9;
        g_xt_dec[j] = (c < 3) ? 0.f : g_tod[b*12 + 0];
    }
}

// ---------------- FP16 diffusion GEMM (ldmatrix, CATt uint4 B-staging) ----------------
__global__ void __launch_bounds__(256) k_graph_h() {
    const int j0 = blockIdx.x * 128;
    const int m0 = blockIdx.y * 128;
    __shared__ __half As[128][24];
    __shared__ __half Bs[128][24];
    __shared__ int coff[128];
    const int tid = threadIdx.x;
    if (tid < 128) {
        int j = j0 + tid;
        coff[tid] = (j / 68) * BSTRIDE + (j % 68);
    }
    __syncthreads();
    const int lane = tid & 31, wid = tid >> 5;
    const int wm = wid & 1, wn = wid >> 1;        // 2 m-warps x 4 n-warps (64x32)
    const int g = lane >> 2, t4 = lane & 3;
    float C[4][4][4];
    #pragma unroll
    for (int i = 0; i < 4; i++)
        #pragma unroll
        for (int j = 0; j < 4; j++)
            #pragma unroll
            for (int r = 0; r < 4; r++) C[i][j][r] = 0.f;

    const int ar = tid >> 1, ak = (tid & 1) * 8;
    const int bn = tid & 127, bk0 = (tid >> 7) * 8;
    const size_t cbT = (size_t)(j0 + bn) * 512;

    const int mat = lane >> 3, l7 = lane & 7;
    const int arow_l = (mat & 1)*8 + l7,  acol_l = (mat >> 1)*8;
    const int brow_l = (mat >> 1)*8 + l7, bcol_l = (mat & 1)*8;
    uint32_t a_addr[4], b_addr[2];
    #pragma unroll
    for (int mi = 0; mi < 4; mi++)
        a_addr[mi] = s2u(&As[wm*64 + mi*16 + arow_l][acol_l]);
    #pragma unroll
    for (int pi = 0; pi < 2; pi++)
        b_addr[pi] = s2u(&Bs[wn*32 + pi*16 + brow_l][bcol_l]);

    for (int k0 = 0; k0 < 512; k0 += 16) {
        *(uint4*)&As[ar][ak]  = *(const uint4*)&g_MMh[(size_t)(m0+ar)*512 + k0 + ak];
        *(uint4*)&Bs[bn][bk0] = *(const uint4*)&g_CATt[cbT + k0 + bk0];
        __syncthreads();
        {
            uint32_t a[4][4], bq[2][4];
            #pragma unroll
            for (int mi = 0; mi < 4; mi++) ldsm4(a[mi], a_addr[mi]);
            #pragma unroll
            for (int pi = 0; pi < 2; pi++) ldsm4(bq[pi], b_addr[pi]);
            #pragma unroll
            for (int mi = 0; mi < 4; mi++)
                #pragma unroll
                for (int ni = 0; ni < 4; ni++)
                    mma_f16(C[mi][ni], a[mi], &bq[ni>>1][(ni&1)*2]);
        }
        __syncthreads();
    }
    #pragma unroll
    for (int mi = 0; mi < 4; mi++) {
        #pragma unroll
        for (int rr = 0; rr < 2; rr++) {
            int m = m0 + wm*64 + mi*16 + g + rr*8;
            int node  = m & 511;
            int obase = (m < 512) ? 68 : 136;
            size_t rbase = (size_t)node * KPAD + obase;
            #pragma unroll
            for (int ni = 0; ni < 4; ni++) {
                int n = wn*32 + ni*8 + 2*t4;   // even; pair (n, n+1) same bp
                __half2 hv = __halves2half2(__float2half_rn(C[mi][ni][rr*2+0]),
                                            __float2half_rn(C[mi][ni][rr*2+1]));
                *(__half2*)&g_CATh[coff[n] + rbase] = hv;
            }
        }
    }
}

// ---------------- FP16 zr gate GEMM + fused temp write (dual layout) ----------------
__global__ void __launch_bounds__(256) k_gatezr_h(int pfix) {
    const int r0 = blockIdx.x * 128;
    const int dec = (pfix == 2);
    const int p = (pfix >= 0) ? pfix : ((r0 < ROWS_DEC) ? 0 : 1);
    const float* H = dec ? g_Hdec : g_H;
    __shared__ __half As[128][24];
    __shared__ __half Bs[128][24];
    const int tid = threadIdx.x;
    const int lane = tid & 31, wid = tid >> 5;
    const int wm = wid & 1, wn = wid >> 1;
    const int g = lane >> 2, t4 = lane & 3;
    float C[4][4][4];
    #pragma unroll
    for (int i = 0; i < 4; i++)
        #pragma unroll
        for (int j = 0; j < 4; j++)
            #pragma unroll
            for (int r = 0; r < 4; r++) C[i][j][r] = 0.f;

    const int ar = tid >> 1, ak = (tid & 1) * 8;
    const int bn = tid & 127, bk0 = (tid >> 7) * 8;
    const __half* Wp = g_Wzrh[p];

    const int mat = lane >> 3, l7 = lane & 7;
    const int arow_l = (mat & 1)*8 + l7,  acol_l = (mat >> 1)*8;
    const int brow_l = (mat >> 1)*8 + l7, bcol_l = (mat & 1)*8;
    uint32_t a_addr[4], b_addr[2];
    #pragma unroll
    for (int mi = 0; mi < 4; mi++)
        a_addr[mi] = s2u(&As[wm*64 + mi*16 + arow_l][acol_l]);
    #pragma unroll
    for (int pi = 0; pi < 2; pi++)
        b_addr[pi] = s2u(&Bs[wn*32 + pi*16 + brow_l][bcol_l]);

    for (int k0 = 0; k0 < KPAD; k0 += 16) {
        *(uint4*)&As[ar][ak] = *(const uint4*)&g_CATh[(size_t)(r0+ar)*KPAD + k0 + ak];
        #pragma unroll
        for (int i = 0; i < 8; i++)
            Bs[bn][bk0+i] = Wp[(k0+bk0+i)*128 + bn];
        __syncthreads();
        {
            uint32_t a[4][4], bq[2][4];
            #pragma unroll
            for (int mi = 0; mi < 4; mi++) ldsm4(a[mi], a_addr[mi]);
            #pragma unroll
            for (int pi = 0; pi < 2; pi++) ldsm4(bq[pi], b_addr[pi]);
            #pragma unroll
            for (int mi = 0; mi < 4; mi++)
                #pragma unroll
                for (int ni = 0; ni < 4; ni++)
                    mma_f16(C[mi][ni], a[mi], &bq[ni>>1][(ni&1)*2]);
        }
        __syncthreads();
    }
    #pragma unroll
    for (int mi = 0; mi < 4; mi++) {
        #pragma unroll
        for (int rr = 0; rr < 2; rr++) {
            int row = r0 + wm*64 + mi*16 + g + rr*8;
            int bp = row >> 9, v = row & 511;
            #pragma unroll
            for (int ni = 0; ni < 4; ni++) {
                #pragma unroll
                for (int q = 0; q < 2; q++) {
                    int col = wn*32 + ni*8 + 2*t4 + q;
                    float val = sigm(C[mi][ni][rr*2+q] + g_bzr[p][col]);
                    if (col < 64) {
                        g_z[(size_t)row*64 + col] = val;
                    } else {
                        int c = col - 64;
                        float h = H[(size_t)row*64 + c];
                        __half hv = __float2half_rn(val*h);
                        g_CATh[(size_t)row*KPAD + 4 + c] = hv;
                        g_CATt[((size_t)bp*68 + 4 + c)*512 + v] = hv;
                    }
                }
            }
        }
    }
}

// ---------------- FP16 C gate GEMM + H update + fused comb/xt write (dual layout) ----------------
__global__ void __launch_bounds__(256) k_gatec_h(int pfix, int dec, const float* __restrict__ xt_next) {
    const int r0 = blockIdx.x * 128;
    const int p = (pfix >= 0) ? pfix : ((r0 < ROWS_DEC) ? 0 : 1);
    float* H = dec ? g_Hdec : g_H;
    __shared__ __half As[128][24];
    __shared__ __half Bs[64][24];
    const int tid = threadIdx.x;
    const int lane = tid & 31, wid = tid >> 5;
    const int wm = wid & 3, wn = wid >> 2;
    const int g = lane >> 2, t4 = lane & 3;
    float C[2][4][4];
    #pragma unroll
    for (int i = 0; i < 2; i++)
        #pragma unroll
        for (int j = 0; j < 4; j++)
            #pragma unroll
            for (int r = 0; r < 4; r++) C[i][j][r] = 0.f;

    const int ar = tid >> 1, ak = (tid & 1) * 8;
    const int bn = tid & 63, bk0 = (tid >> 6) * 4;
    const __half* Wp = g_Wch[p];

    const int mat = lane >> 3, l7 = lane & 7;
    const int arow_l = (mat & 1)*8 + l7,  acol_l = (mat >> 1)*8;
    const int brow_l = (mat >> 1)*8 + l7, bcol_l = (mat & 1)*8;
    uint32_t a_addr[2], b_addr[2];
    #pragma unroll
    for (int mi = 0; mi < 2; mi++)
        a_addr[mi] = s2u(&As[wm*32 + mi*16 + arow_l][acol_l]);
    #pragma unroll
    for (int pi = 0; pi < 2; pi++)
        b_addr[pi] = s2u(&Bs[wn*32 + pi*16 + brow_l][bcol_l]);

    for (int k0 = 0; k0 < KPAD; k0 += 16) {
        *(uint4*)&As[ar][ak] = *(const uint4*)&g_CATh[(size_t)(r0+ar)*KPAD + k0 + ak];
        #pragma unroll
        for (int i = 0; i < 4; i++)
            Bs[bn][bk0+i] = Wp[(k0+bk0+i)*64 + bn];
        __syncthreads();
        {
            uint32_t a[2][4], bq[2][4];
            #pragma unroll
            for (int mi = 0; mi < 2; mi++) ldsm4(a[mi], a_addr[mi]);
            #pragma unroll
            for (int pi = 0; pi < 2; pi++) ldsm4(bq[pi], b_addr[pi]);
            #pragma unroll
            for (int mi = 0; mi < 2; mi++)
                #pragma unroll
                for (int ni = 0; ni < 4; ni++)
                    mma_f16(C[mi][ni], a[mi], &bq[ni>>1][(ni&1)*2]);
        }
        __syncthreads();
    }
    #pragma unroll
    for (int mi = 0; mi < 2; mi++) {
        #pragma unroll
        for (int rr = 0; rr < 2; rr++) {
            int row = r0 + wm*32 + mi*16 + g + rr*8;
            int bp = row >> 9, v = row & 511;
            #pragma unroll
            for (int ni = 0; ni < 4; ni++) {
                #pragma unroll
                for (int q = 0; q < 2; q++) {
                    int col = wn*32 + ni*8 + 2*t4 + q;
                    float c = tanhf(C[mi][ni][rr*2+q] + g_bc[p][col]);
                    float z = g_z[(size_t)row*64 + col];
                    float h = H[(size_t)row*64 + col];
                    float hn = z*h + (1.f - z)*c;
                    H[(size_t)row*64 + col] = hn;
                    __half hv = __float2half_rn(hn);
                    g_CATh[(size_t)row*KPAD + 4 + col] = hv;
                    g_CATt[((size_t)bp*68 + 4 + col)*512 + v] = hv;
                    if (xt_next != nullptr && col < 4) {
                        __half xv = __float2half_rn(xt_next[(size_t)row*4 + col]);
                        g_CATh[(size_t)row*KPAD + col] = xv;
                        g_CATt[((size_t)bp*68 + col)*512 + v] = xv;
                    }
                }
            }
        }
    }
}

// ---------------- mix GEMM + fused comb write for decoder step 0 (dual layout) ----------------
__global__ void __launch_bounds__(256) k_mix() {
    const int r0 = blockIdx.x * 128;
    __shared__ float As[8][128];
    __shared__ float Bs[8][64];
    const int tid = threadIdx.x;
    float acc[8][4];
    #pragma unroll
    for (int i = 0; i < 8; i++)
        #pragma unroll
        for (int j = 0; j < 4; j++) acc[i][j] = 0.f;

    const int arow = tid >> 1, acol = (tid & 1) * 4;
    const int tx = tid & 15, ty = tid >> 4;

    for (int k0 = 0; k0 < 128; k0 += 8) {
        int row = r0 + arow;
        const float* src = (k0 < 64) ? &g_H[(size_t)row*64 + k0 + acol]
                                     : &g_H[((size_t)row + ROWS_DEC)*64 + (k0 - 64) + acol];
        float4 av = *(const float4*)src;
        As[acol+0][arow] = av.x; As[acol+1][arow] = av.y;
        As[acol+2][arow] = av.z; As[acol+3][arow] = av.w;
        #pragma unroll
        for (int r = 0; r < 2; r++) {
            int ii = tid + r*256;
            int k = ii >> 6, j = ii & 63;
            Bs[k][j] = g_Wmix[(k0+k)*64 + j];
        }
        __syncthreads();
        #pragma unroll
        for (int kk = 0; kk < 8; kk++) {
            float4 a0 = *(const float4*)&As[kk][ty*8];
            float4 a1 = *(const float4*)&As[kk][ty*8+4];
            float4 b0 = *(const float4*)&Bs[kk][tx*4];
            float aa[8] = {a0.x,a0.y,a0.z,a0.w,a1.x,a1.y,a1.z,a1.w};
            float bb[4] = {b0.x,b0.y,b0.z,b0.w};
            #pragma unroll
            for (int i = 0; i < 8; i++)
                #pragma unroll
                for (int j = 0; j < 4; j++)
                    acc[i][j] += aa[i]*bb[j];
        }
        __syncthreads();
    }
    #pragma unroll
    for (int i = 0; i < 8; i++) {
        int row = r0 + ty*8 + i;
        int bp = row >> 9, v = row & 511;
        #pragma unroll
        for (int j = 0; j < 4; j++) {
            int col = tx*4 + j;
            float hv = acc[i][j] + g_bmix[col];
            g_Hdec[(size_t)row*64 + col] = hv;
            __half h2 = __float2half_rn(hv);
            g_CATh[(size_t)row*KPAD + 4 + col] = h2;
            g_CATt[((size_t)bp*68 + 4 + col)*512 + v] = h2;
            if (col < 4) {
                __half xv = __float2half_rn(g_xt_dec[(size_t)row*4 + col]);
                g_CATh[(size_t)row*KPAD + col] = xv;
                g_CATt[((size_t)bp*68 + col)*512 + v] = xv;
            }
        }
    }
}

// ---------------- decoder FC + output scatter + fused next-xt comb write (dual layout) ----------------
__global__ void k_fc(const float* __restrict__ Wfc, const float* __restrict__ bfc,
                     float* __restrict__ out, int t) {
    int row = blockIdx.x*blockDim.x + threadIdx.x;
    if (row >= ROWS_DEC) return;
    int b = row >> 9, n = row & 511;
    int bp = row >> 9;
    float a0 = bfc[0], a1 = bfc[1], a2 = bfc[2];
    const float* h = &g_Hdec[(size_t)row*64];
    #pragma unroll 8
    for (int k = 0; k < 64; k++) {
        float hv = h[k];
        a0 += hv * Wfc[k*3+0];
        a1 += hv * Wfc[k*3+1];
        a2 += hv * Wfc[k*3+2];
    }
    float av[3] = {a0, a1, a2};
    #pragma unroll
    for (int d = 0; d < 3; d++) {
        int L = 3*t + d;
        int dp = L / 12, tp = L % 12;
        out[((b*3+dp)*512 + n)*12 + tp] = av[d];
        __half xv = __float2half_rn(av[d]);
        g_CATh[(size_t)row*KPAD + d] = xv;
        g_CATt[((size_t)bp*68 + d)*512 + n] = xv;
    }
    if (t + 1 < 12) {
        __half tv = __float2half_rn(g_tod[b*12 + t + 1]);
        g_CATh[(size_t)row*KPAD + 3] = tv;
        g_CATt[((size_t)bp*68 + 3)*512 + n] = tv;
    }
}

// ---------------- launch ----------------
extern "C" void kernel_launch(void* const* d_in, const int* in_sizes, int n_in,
                              void* d_out, int out_size) {
    const float* x   = (const float*)d_in[0];
    const float* st  = (const float*)d_in[2];
    const float* A   = (const float*)d_in[3];
    const float* Wg  = (const float*)d_in[4];
    const float* bg  = (const float*)d_in[5];
    const float* Wm  = (const float*)d_in[6];
    const float* bm  = (const float*)d_in[7];
    const float* Wi  = (const float*)d_in[8];
    const float* bi  = (const float*)d_in[9];
    const float* Wfc = (const float*)d_in[10];
    const float* bfc = (const float*)d_in[11];
    float* out = (float*)d_out;

    static float* xt_enc_base = nullptr;
    if (!xt_enc_base) cudaGetSymbolAddress((void**)&xt_enc_base, g_xt_enc);

    // prep
    k_rowsum<<<512, 128>>>(A);
    k_P<<<1024, 256>>>(A);
    k_M2<<<1024, 256>>>();
    k_weights<<<(3*204*128 + 3*204*64 + 3*128 + 3*64 + 255)/256, 256>>>(Wg, bg);
    k_mixw<<<(4160 + 255)/256, 256>>>(Wi, bi, Wm, bm);
    k_tod<<<3, 256>>>(st);
    k_xt_enc<<<(6*ROWS_ENC*4)/256, 256>>>(x, st);
    k_init_state<<<((size_t)ROWS_ENC*68 + ROWS_DEC*4 + 255)/256, 256>>>();

    // encoders (D + A batched: 128 batch-slices)
    for (int t = 0; t < 6; t++) {
        k_graph_h<<<dim3(68, 8), 256>>>();
        k_gatezr_h<<<ROWS_ENC/128, 256>>>(-1);
        k_graph_h<<<dim3(68, 8), 256>>>();
        const float* xtn = (t < 5) ? (xt_enc_base + (size_t)(t+1)*ROWS_ENC*4) : nullptr;
        k_gatec_h<<<ROWS_ENC/128, 256>>>(-1, 0, xtn);
    }

    // mix -> decoder initial H + comb
    k_mix<<<ROWS_DEC/128, 256>>>();

    // decoder
    for (int t = 0; t < 12; t++) {
        k_graph_h<<<dim3(34, 8), 256>>>();
        k_gatezr_h<<<ROWS_DEC/128, 256>>>(2);
        k_graph_h<<<dim3(34, 8), 256>>>();
        k_gatec_h<<<ROWS_DEC/128, 256>>>(2, 1, nullptr);
        k_fc<<<ROWS_DEC/256, 256>>>(Wfc, bfc, out, t);
    }
}

// round 15
// speedup vs baseline: 1.1079x; 1.1079x over previous
#include <cuda_runtime.h>
#include <cuda_fp16.h>
#include <math.h>
#include <stdint.h>

#define NNODE   512
#define KPAD    208
#define ROWS_ENC (128*512)   // 65536
#define ROWS_DEC (64*512)    // 32768
#define BSTRIDE  (512*KPAD)
#define INV_S2  0.70710678118654752440f

// ---------------- scratch (device globals; no allocation) ----------------
__device__ __align__(16) __half g_MMh[1024*512];      // [M1;M2] fp16, K contiguous
__device__ __align__(16) float  g_P[512*512];
__device__ float g_rs[512];
__device__ __align__(16) __half g_CATh[ROWS_ENC*KPAD]; // row-major: comb(68)|Q1(68)|Q2(68)|pad0
__device__ __align__(16) float g_H[ROWS_ENC*64];
__device__ __align__(16) float g_Hdec[ROWS_DEC*64];
__device__ __align__(16) float g_z[ROWS_ENC*64];
__device__ __align__(16) float g_xt_enc[6*ROWS_ENC*4];
__device__ __align__(16) float g_xt_dec[ROWS_DEC*4];
__device__ float g_tod[64*12];
__device__ __align__(16) __half g_Wzrh[3][KPAD*128];  // [k][g], rows 204..207 zero
__device__ float g_bzr[3][128];
__device__ __align__(16) __half g_Wch[3][KPAD*64];    // [k][c]
__device__ float g_bc[3][64];
__device__ __align__(16) float g_Wmix[128*64];
__device__ float g_bmix[64];

// ---------------- helpers ----------------
__device__ __forceinline__ void mma_f16(float* d, const uint32_t* a, const uint32_t* b) {
    asm volatile(
        "mma.sync.aligned.m16n8k16.row.col.f32.f16.f16.f32 "
        "{%0,%1,%2,%3}, {%4,%5,%6,%7}, {%8,%9}, {%0,%1,%2,%3};"
        : "+f"(d[0]), "+f"(d[1]), "+f"(d[2]), "+f"(d[3])
        : "r"(a[0]), "r"(a[1]), "r"(a[2]), "r"(a[3]), "r"(b[0]), "r"(b[1]));
}
__device__ __forceinline__ float sigm(float x) { return 1.f / (1.f + __expf(-x)); }
__device__ __forceinline__ uint32_t s2u(const void* p) {
    return (uint32_t)__cvta_generic_to_shared(p);
}
__device__ __forceinline__ void ldsm4(uint32_t* r, uint32_t a) {
    asm volatile("ldmatrix.sync.aligned.m8n8.x4.shared.b16 {%0,%1,%2,%3}, [%4];"
        : "=r"(r[0]), "=r"(r[1]), "=r"(r[2]), "=r"(r[3]) : "r"(a));
}

// ---------------- prep ----------------
__global__ void k_rowsum(const float* __restrict__ A) {
    int v = blockIdx.x;
    float s = 0.f;
    for (int w = threadIdx.x; w < 512; w += 128) s += A[v*512+w];
    __shared__ float sh[128];
    sh[threadIdx.x] = s; __syncthreads();
    for (int o = 64; o > 0; o >>= 1) {
        if (threadIdx.x < o) sh[threadIdx.x] += sh[threadIdx.x+o];
        __syncthreads();
    }
    if (threadIdx.x == 0) g_rs[v] = sh[0] + 1.0f;
}

__global__ void k_P(const float* __restrict__ A) {
    int idx = blockIdx.x*blockDim.x + threadIdx.x;
    if (idx >= 512*512) return;
    int w = idx >> 9, v = idx & 511;
    float a  = A[v*512+w];
    float an = (a + (v==w ? 1.f : 0.f)) / g_rs[v];
    float p  = 0.95f*an + 0.95f*a;
    g_P[w*512+v]   = p;
    g_MMh[w*512+v] = __float2half_rn((v==w ? 0.05f : 0.f) + p);   // M1
}

__global__ void k_M2() {
    int idx = blockIdx.x*blockDim.x + threadIdx.x;
    if (idx >= 512*512) return;
    int w = idx >> 9, v = idx & 511;
    const float* pw = g_P + w*512;
    float s = 0.f;
    #pragma unroll 8
    for (int u = 0; u < 512; u++) s += pw[u] * g_P[u*512+v];
    g_MMh[(512+w)*512+v] = __float2half_rn((w==v ? 0.05f : 0.f) + 0.05f*g_P[w*512+v] + s); // M2
}

__global__ void k_weights(const float* __restrict__ Wg, const float* __restrict__ bg) {
    int idx = blockIdx.x*blockDim.x + threadIdx.x;
    const int TZR = 3*204*128, TC = 3*204*64;
    if (idx < TZR) {
        int p = idx / (204*128); int rem = idx % (204*128);
        int k = rem / 128, g = rem % 128;
        int gate = (g < 64) ? 0 : 2;  int c = g & 63;
        int w1 = 6*p + gate;
        g_Wzrh[p][k*128+g] = __float2half_rn(Wg[(w1*204+k)*64+c] + Wg[((w1+1)*204+k)*64+c]);
    } else if (idx < TZR + TC) {
        int j = idx - TZR;
        int p = j / (204*64); int rem = j % (204*64);
        int k = rem / 64, c = rem % 64;
        int w1 = 6*p + 4;
        g_Wch[p][k*64+c] = __float2half_rn(Wg[(w1*204+k)*64+c] + Wg[((w1+1)*204+k)*64+c]);
    } else if (idx < TZR + TC + 3*128) {
        int j = idx - TZR - TC;
        int p = j / 128, g = j % 128;
        int gate = (g < 64) ? 0 : 2; int c = g & 63;
        g_bzr[p][g] = bg[(6*p+gate)*64+c] + bg[(6*p+gate+1)*64+c];
    } else if (idx < TZR + TC + 3*128 + 3*64) {
        int j = idx - TZR - TC - 3*128;
        int p = j / 64, c = j % 64;
        g_bc[p][c] = bg[(6*p+4)*64+c] + bg[(6*p+5)*64+c];
    }
}

__global__ void k_mixw(const float* __restrict__ Wi, const float* __restrict__ bi,
                       const float* __restrict__ Wm, const float* __restrict__ bm) {
    int idx = blockIdx.x*blockDim.x + threadIdx.x;
    if (idx < 4096) {
        int k = idx >> 6, c = idx & 63;
        float s = 0.f;
        for (int j = 0; j < 64; j++) {
            s += Wi[k*64+j]        * Wm[(256+2*j  )*64+c]
               + Wi[4096 + k*64+j] * Wm[(256+2*j+1)*64+c];
        }
        g_Wmix[k*64+c]      = 0.3f*s + 0.7f*Wm[(128+k)*64+c];
        g_Wmix[(64+k)*64+c] = 0.3f*s + 0.7f*Wm[(128+64+k)*64+c];
    } else if (idx < 4096 + 64) {
        int c = idx - 4096;
        float s = 0.f;
        for (int j = 0; j < 64; j++)
            s += 2.f*bi[j]    * Wm[(256+2*j  )*64+c]
               + 2.f*bi[64+j] * Wm[(256+2*j+1)*64+c];
        g_bmix[c] = 0.3f*(s + bm[128+c]) + 0.7f*bm[64+c];
    }
}

__global__ void k_tod(const float* __restrict__ st) {
    int idx = blockIdx.x*blockDim.x + threadIdx.x;
    if (idx >= 64*12) return;
    int b = idx / 12, t = idx % 12;
    g_tod[idx] = (float)(int)((st[(b*5+2)*12+t] + 0.5f) * 6.0f);
}

__global__ void k_xt_enc(const float* __restrict__ x, const float* __restrict__ st) {
    int idx = blockIdx.x*blockDim.x + threadIdx.x;
    if (idx >= 6*ROWS_ENC*4) return;
    int c   = idx & 3;
    int rem = idx >> 2;
    int row = rem & (ROWS_ENC-1);
    int t   = rem >> 16;
    int bp = row >> 9, n = row & 511;
    int b = bp & 63;
    float val;
    if (c < 3) {
        float xe = x[((b*3+c)*512+n)*12 + 2*t];
        float xo = x[((b*3+c)*512+n)*12 + 2*t + 1];
        val = ((bp < 64) ? (xe - xo) : (xe + xo)) * INV_S2;
    } else {
        int s = 2*t;
        float hour   = (st[(b*5+3)*12+s] + 0.5f) * 23.0f;
        float minute = (st[(b*5+4)*12+s] + 0.5f) * 59.0f;
        val = (float)(int)((hour*60.0f + minute) / 5.0f);
    }
    g_xt_enc[idx] = val;
}

// init: H=0, CATh comb for enc t=0 = [xt_enc(0) | 0], xt_dec init
__global__ void k_init_state() {
    int idx = blockIdx.x*blockDim.x + threadIdx.x;
    if (idx < ROWS_ENC*68) {
        int row = idx / 68, c = idx - row*68;
        if (c < 4) {
            g_CATh[(size_t)row*KPAD + c] = __float2half_rn(g_xt_enc[row*4 + c]);
        } else {
            g_CATh[(size_t)row*KPAD + c] = __float2half_rn(0.f);
            g_H[(size_t)row*64 + (c-4)] = 0.f;
        }
        return;
    }
    int j = idx - ROWS_ENC*68;
    if (j < ROWS_DEC*4) {
        int c = j & 3; int row = j >> 2; int b = row >> 9;
        g_xt_dec[j] = (c < 3) ? 0.f : g_tod[b*12 + 0];
    }
}

// ---------------- FP16 diffusion GEMM (ldmatrix, K-tile=32) ----------------
__global__ void __launch_bounds__(256) k_graph_h() {
    const int j0 = blockIdx.x * 128;
    const int m0 = blockIdx.y * 128;
    __shared__ __half As[128][40];
    __shared__ __half Bs[128][40];
    __shared__ int coff[128];
    const int tid = threadIdx.x;
    if (tid < 128) {
        int j = j0 + tid;
        coff[tid] = (j / 68) * BSTRIDE + (j % 68);
    }
    __syncthreads();
    const int lane = tid & 31, wid = tid >> 5;
    const int wm = wid & 1, wn = wid >> 1;        // 2 m-warps x 4 n-warps (64x32)
    const int g = lane >> 2, t4 = lane & 3;
    float C[4][4][4];
    #pragma unroll
    for (int i = 0; i < 4; i++)
        #pragma unroll
        for (int j = 0; j < 4; j++)
            #pragma unroll
            for (int r = 0; r < 4; r++) C[i][j][r] = 0.f;

    const int ar = tid >> 1, ak = (tid & 1) * 16;
    const int bn = tid & 127, bk0 = (tid >> 7) * 16;
    const int cb = coff[bn];

    // ldmatrix lane addresses (k0-invariant):
    // A order: (rows0-7,k0-7)(rows8-15,k0-7)(rows0-7,k8-15)(rows8-15,k8-15)
    // B order: (rows0-7,k0-7)(rows0-7,k8-15)(rows8-15,k0-7)(rows8-15,k8-15)
    const int mat = lane >> 3, l7 = lane & 7;
    const int arow_l = (mat & 1)*8 + l7,  acol_l = (mat >> 1)*8;
    const int brow_l = (mat >> 1)*8 + l7, bcol_l = (mat & 1)*8;
    uint32_t a_addr[4], b_addr[2];
    #pragma unroll
    for (int mi = 0; mi < 4; mi++)
        a_addr[mi] = s2u(&As[wm*64 + mi*16 + arow_l][acol_l]);
    #pragma unroll
    for (int pi = 0; pi < 2; pi++)
        b_addr[pi] = s2u(&Bs[wn*32 + pi*16 + brow_l][bcol_l]);

    for (int k0 = 0; k0 < 512; k0 += 32) {
        *(uint4*)&As[ar][ak]     = *(const uint4*)&g_MMh[(size_t)(m0+ar)*512 + k0 + ak];
        *(uint4*)&As[ar][ak + 8] = *(const uint4*)&g_MMh[(size_t)(m0+ar)*512 + k0 + ak + 8];
        #pragma unroll
        for (int i = 0; i < 16; i++)
            Bs[bn][bk0+i] = g_CATh[(size_t)cb + (size_t)(k0+bk0+i)*KPAD];
        __syncthreads();
        #pragma unroll
        for (int kc = 0; kc < 2; kc++) {
            uint32_t a[4][4], bq[2][4];
            #pragma unroll
            for (int mi = 0; mi < 4; mi++) ldsm4(a[mi], a_addr[mi] + kc*32);
            #pragma unroll
            for (int pi = 0; pi < 2; pi++) ldsm4(bq[pi], b_addr[pi] + kc*32);
            #pragma unroll
            for (int mi = 0; mi < 4; mi++)
                #pragma unroll
                for (int ni = 0; ni < 4; ni++)
                    mma_f16(C[mi][ni], a[mi], &bq[ni>>1][(ni&1)*2]);
        }
        __syncthreads();
    }
    #pragma unroll
    for (int mi = 0; mi < 4; mi++) {
        #pragma unroll
        for (int rr = 0; rr < 2; rr++) {
            int m = m0 + wm*64 + mi*16 + g + rr*8;
            int node  = m & 511;
            int obase = (m < 512) ? 68 : 136;
            size_t rbase = (size_t)node * KPAD + obase;
            #pragma unroll
            for (int ni = 0; ni < 4; ni++) {
                int n = wn*32 + ni*8 + 2*t4;   // even; pair (n, n+1) same bp
                __half2 hv = __halves2half2(__float2half_rn(C[mi][ni][rr*2+0]),
                                            __float2half_rn(C[mi][ni][rr*2+1]));
                *(__half2*)&g_CATh[coff[n] + rbase] = hv;
            }
        }
    }
}

// ---------------- FP16 zr gate GEMM + fused temp write (ldmatrix) ----------------
__global__ void __launch_bounds__(256) k_gatezr_h(int pfix) {
    const int r0 = blockIdx.x * 128;
    const int dec = (pfix == 2);
    const int p = (pfix >= 0) ? pfix : ((r0 < ROWS_DEC) ? 0 : 1);
    const float* H = dec ? g_Hdec : g_H;
    __shared__ __half As[128][24];
    __shared__ __half Bs[128][24];
    const int tid = threadIdx.x;
    const int lane = tid & 31, wid = tid >> 5;
    const int wm = wid & 1, wn = wid >> 1;
    const int g = lane >> 2, t4 = lane & 3;
    float C[4][4][4];
    #pragma unroll
    for (int i = 0; i < 4; i++)
        #pragma unroll
        for (int j = 0; j < 4; j++)
            #pragma unroll
            for (int r = 0; r < 4; r++) C[i][j][r] = 0.f;

    const int ar = tid >> 1, ak = (tid & 1) * 8;
    const int bn = tid & 127, bk0 = (tid >> 7) * 8;
    const __half* Wp = g_Wzrh[p];

    const int mat = lane >> 3, l7 = lane & 7;
    const int arow_l = (mat & 1)*8 + l7,  acol_l = (mat >> 1)*8;
    const int brow_l = (mat >> 1)*8 + l7, bcol_l = (mat & 1)*8;
    uint32_t a_addr[4], b_addr[2];
    #pragma unroll
    for (int mi = 0; mi < 4; mi++)
        a_addr[mi] = s2u(&As[wm*64 + mi*16 + arow_l][acol_l]);
    #pragma unroll
    for (int pi = 0; pi < 2; pi++)
        b_addr[pi] = s2u(&Bs[wn*32 + pi*16 + brow_l][bcol_l]);

    for (int k0 = 0; k0 < KPAD; k0 += 16) {
        *(uint4*)&As[ar][ak] = *(const uint4*)&g_CATh[(size_t)(r0+ar)*KPAD + k0 + ak];
        #pragma unroll
        for (int i = 0; i < 8; i++)
            Bs[bn][bk0+i] = Wp[(k0+bk0+i)*128 + bn];
        __syncthreads();
        {
            uint32_t a[4][4], bq[2][4];
            #pragma unroll
            for (int mi = 0; mi < 4; mi++) ldsm4(a[mi], a_addr[mi]);
            #pragma unroll
            for (int pi = 0; pi < 2; pi++) ldsm4(bq[pi], b_addr[pi]);
            #pragma unroll
            for (int mi = 0; mi < 4; mi++)
                #pragma unroll
                for (int ni = 0; ni < 4; ni++)
                    mma_f16(C[mi][ni], a[mi], &bq[ni>>1][(ni&1)*2]);
        }
        __syncthreads();
    }
    #pragma unroll
    for (int mi = 0; mi < 4; mi++) {
        #pragma unroll
        for (int rr = 0; rr < 2; rr++) {
            int row = r0 + wm*64 + mi*16 + g + rr*8;
            #pragma unroll
            for (int ni = 0; ni < 4; ni++) {
                #pragma unroll
                for (int q = 0; q < 2; q++) {
                    int col = wn*32 + ni*8 + 2*t4 + q;
                    float v = sigm(C[mi][ni][rr*2+q] + g_bzr[p][col]);
                    if (col < 64) {
                        g_z[(size_t)row*64 + col] = v;
                    } else {
                        int c = col - 64;
                        float h = H[(size_t)row*64 + c];
                        g_CATh[(size_t)row*KPAD + 4 + c] = __float2half_rn(v*h);
                    }
                }
            }
        }
    }
}

// ---------------- FP16 C gate GEMM + H update + fused comb/xt write (ldmatrix) ----------------
__global__ void __launch_bounds__(256) k_gatec_h(int pfix, int dec, const float* __restrict__ xt_next) {
    const int r0 = blockIdx.x * 128;
    const int p = (pfix >= 0) ? pfix : ((r0 < ROWS_DEC) ? 0 : 1);
    float* H = dec ? g_Hdec : g_H;
    __shared__ __half As[128][24];
    __shared__ __half Bs[64][24];
    const int tid = threadIdx.x;
    const int lane = tid & 31, wid = tid >> 5;
    const int wm = wid & 3, wn = wid >> 2;
    const int g = lane >> 2, t4 = lane & 3;
    float C[2][4][4];
    #pragma unroll
    for (int i = 0; i < 2; i++)
        #pragma unroll
        for (int j = 0; j < 4; j++)
            #pragma unroll
            for (int r = 0; r < 4; r++) C[i][j][r] = 0.f;

    const int ar = tid >> 1, ak = (tid & 1) * 8;
    const int bn = tid & 63, bk0 = (tid >> 6) * 4;
    const __half* Wp = g_Wch[p];

    const int mat = lane >> 3, l7 = lane & 7;
    const int arow_l = (mat & 1)*8 + l7,  acol_l = (mat >> 1)*8;
    const int brow_l = (mat >> 1)*8 + l7, bcol_l = (mat & 1)*8;
    uint32_t a_addr[2], b_addr[2];
    #pragma unroll
    for (int mi = 0; mi < 2; mi++)
        a_addr[mi] = s2u(&As[wm*32 + mi*16 + arow_l][acol_l]);
    #pragma unroll
    for (int pi = 0; pi < 2; pi++)
        b_addr[pi] = s2u(&Bs[wn*32 + pi*16 + brow_l][bcol_l]);

    for (int k0 = 0; k0 < KPAD; k0 += 16) {
        *(uint4*)&As[ar][ak] = *(const uint4*)&g_CATh[(size_t)(r0+ar)*KPAD + k0 + ak];
        #pragma unroll
        for (int i = 0; i < 4; i++)
            Bs[bn][bk0+i] = Wp[(k0+bk0+i)*64 + bn];
        __syncthreads();
        {
            uint32_t a[2][4], bq[2][4];
            #pragma unroll
            for (int mi = 0; mi < 2; mi++) ldsm4(a[mi], a_addr[mi]);
            #pragma unroll
            for (int pi = 0; pi < 2; pi++) ldsm4(bq[pi], b_addr[pi]);
            #pragma unroll
            for (int mi = 0; mi < 2; mi++)
                #pragma unroll
                for (int ni = 0; ni < 4; ni++)
                    mma_f16(C[mi][ni], a[mi], &bq[ni>>1][(ni&1)*2]);
        }
        __syncthreads();
    }
    #pragma unroll
    for (int mi = 0; mi < 2; mi++) {
        #pragma unroll
        for (int rr = 0; rr < 2; rr++) {
            int row = r0 + wm*32 + mi*16 + g + rr*8;
            #pragma unroll
            for (int ni = 0; ni < 4; ni++) {
                #pragma unroll
                for (int q = 0; q < 2; q++) {
                    int col = wn*32 + ni*8 + 2*t4 + q;
                    float c = tanhf(C[mi][ni][rr*2+q] + g_bc[p][col]);
                    float z = g_z[(size_t)row*64 + col];
                    float h = H[(size_t)row*64 + col];
                    float hn = z*h + (1.f - z)*c;
                    H[(size_t)row*64 + col] = hn;
                    g_CATh[(size_t)row*KPAD + 4 + col] = __float2half_rn(hn);
                    if (xt_next != nullptr && col < 4)
                        g_CATh[(size_t)row*KPAD + col] =
                            __float2half_rn(xt_next[(size_t)row*4 + col]);
                }
            }
        }
    }
}

// ---------------- mix GEMM + fused comb write for decoder step 0 ----------------
__global__ void __launch_bounds__(256) k_mix() {
    const int r0 = blockIdx.x * 128;
    __shared__ float As[8][128];
    __shared__ float Bs[8][64];
    const int tid = threadIdx.x;
    float acc[8][4];
    #pragma unroll
    for (int i = 0; i < 8; i++)
        #pragma unroll
        for (int j = 0; j < 4; j++) acc[i][j] = 0.f;

    const int arow = tid >> 1, acol = (tid & 1) * 4;
    const int tx = tid & 15, ty = tid >> 4;

    for (int k0 = 0; k0 < 128; k0 += 8) {
        int row = r0 + arow;
        const float* src = (k0 < 64) ? &g_H[(size_t)row*64 + k0 + acol]
                                     : &g_H[((size_t)row + ROWS_DEC)*64 + (k0 - 64) + acol];
        float4 av = *(const float4*)src;
        As[acol+0][arow] = av.x; As[acol+1][arow] = av.y;
        As[acol+2][arow] = av.z; As[acol+3][arow] = av.w;
        #pragma unroll
        for (int r = 0; r < 2; r++) {
            int ii = tid + r*256;
            int k = ii >> 6, j = ii & 63;
            Bs[k][j] = g_Wmix[(k0+k)*64 + j];
        }
        __syncthreads();
        #pragma unroll
        for (int kk = 0; kk < 8; kk++) {
            float4 a0 = *(const float4*)&As[kk][ty*8];
            float4 a1 = *(const float4*)&As[kk][ty*8+4];
            float4 b0 = *(const float4*)&Bs[kk][tx*4];
            float aa[8] = {a0.x,a0.y,a0.z,a0.w,a1.x,a1.y,a1.z,a1.w};
            float bb[4] = {b0.x,b0.y,b0.z,b0.w};
            #pragma unroll
            for (int i = 0; i < 8; i++)
                #pragma unroll
                for (int j = 0; j < 4; j++)
                    acc[i][j] += aa[i]*bb[j];
        }
        __syncthreads();
    }
    #pragma unroll
    for (int i = 0; i < 8; i++) {
        int row = r0 + ty*8 + i;
        #pragma unroll
        for (int j = 0; j < 4; j++) {
            int col = tx*4 + j;
            float hv = acc[i][j] + g_bmix[col];
            g_Hdec[(size_t)row*64 + col] = hv;
            g_CATh[(size_t)row*KPAD + 4 + col] = __float2half_rn(hv);
            if (col < 4)
                g_CATh[(size_t)row*KPAD + col] =
                    __float2half_rn(g_xt_dec[(size_t)row*4 + col]);
        }
    }
}

// ---------------- decoder FC + output scatter + fused next-xt comb write ----------------
__global__ void k_fc(const float* __restrict__ Wfc, const float* __restrict__ bfc,
                     float* __restrict__ out, int t) {
    int row = blockIdx.x*blockDim.x + threadIdx.x;
    if (row >= ROWS_DEC) return;
    int b = row >> 9, n = row & 511;
    float a0 = bfc[0], a1 = bfc[1], a2 = bfc[2];
    const float* h = &g_Hdec[(size_t)row*64];
    #pragma unroll 8
    for (int k = 0; k < 64; k++) {
        float hv = h[k];
        a0 += hv * Wfc[k*3+0];
        a1 += hv * Wfc[k*3+1];
        a2 += hv * Wfc[k*3+2];
    }
    float av[3] = {a0, a1, a2};
    #pragma unroll
    for (int d = 0; d < 3; d++) {
        int L = 3*t + d;
        int dp = L / 12, tp = L % 12;
        out[((b*3+dp)*512 + n)*12 + tp] = av[d];
        g_CATh[(size_t)row*KPAD + d] = __float2half_rn(av[d]);
    }
    if (t + 1 < 12)
        g_CATh[(size_t)row*KPAD + 3] = __float2half_rn(g_tod[b*12 + t + 1]);
}

// ---------------- launch ----------------
extern "C" void kernel_launch(void* const* d_in, const int* in_sizes, int n_in,
                              void* d_out, int out_size) {
    const float* x   = (const float*)d_in[0];
    const float* st  = (const float*)d_in[2];
    const float* A   = (const float*)d_in[3];
    const float* Wg  = (const float*)d_in[4];
    const float* bg  = (const float*)d_in[5];
    const float* Wm  = (const float*)d_in[6];
    const float* bm  = (const float*)d_in[7];
    const float* Wi  = (const float*)d_in[8];
    const float* bi  = (const float*)d_in[9];
    const float* Wfc = (const float*)d_in[10];
    const float* bfc = (const float*)d_in[11];
    float* out = (float*)d_out;

    static float* xt_enc_base = nullptr;
    if (!xt_enc_base) cudaGetSymbolAddress((void**)&xt_enc_base, g_xt_enc);

    // prep
    k_rowsum<<<512, 128>>>(A);
    k_P<<<1024, 256>>>(A);
    k_M2<<<1024, 256>>>();
    k_weights<<<(3*204*128 + 3*204*64 + 3*128 + 3*64 + 255)/256, 256>>>(Wg, bg);
    k_mixw<<<(4160 + 255)/256, 256>>>(Wi, bi, Wm, bm);
    k_tod<<<3, 256>>>(st);
    k_xt_enc<<<(6*ROWS_ENC*4)/256, 256>>>(x, st);
    k_init_state<<<((size_t)ROWS_ENC*68 + ROWS_DEC*4 + 255)/256, 256>>>();

    // encoders (D + A batched: 128 batch-slices)
    for (int t = 0; t < 6; t++) {
        k_graph_h<<<dim3(68, 8), 256>>>();
        k_gatezr_h<<<ROWS_ENC/128, 256>>>(-1);
        k_graph_h<<<dim3(68, 8), 256>>>();
        const float* xtn = (t < 5) ? (xt_enc_base + (size_t)(t+1)*ROWS_ENC*4) : nullptr;
        k_gatec_h<<<ROWS_ENC/128, 256>>>(-1, 0, xtn);
    }

    // mix -> decoder initial H + comb
    k_mix<<<ROWS_DEC/128, 256>>>();

    // decoder
    for (int t = 0; t < 12; t++) {
        k_graph_h<<<dim3(34, 8), 256>>>();
        k_gatezr_h<<<ROWS_DEC/128, 256>>>(2);
        k_graph_h<<<dim3(34, 8), 256>>>();
        k_gatec_h<<<ROWS_DEC/128, 256>>>(2, 1, nullptr);
        k_fc<<<ROWS_DEC/256, 256>>>(Wfc, bfc, out, t);
    }
}

// round 16
// speedup vs baseline: 1.1267x; 1.0170x over previous
#include <cuda_runtime.h>
#include <cuda_fp16.h>
#include <math.h>
#include <stdint.h>

#define NNODE   512
#define KPAD    224          // padded to 7*32; cols/rows 204..223 stay zero (bss)
#define ROWS_ENC (128*512)   // 65536
#define ROWS_DEC (64*512)    // 32768
#define BSTRIDE  (512*KPAD)
#define INV_S2  0.70710678118654752440f

// ---------------- scratch (device globals; no allocation) ----------------
__device__ __align__(16) __half g_MMh[1024*512];      // [M1;M2] fp16, K contiguous
__device__ __align__(16) float  g_P[512*512];
__device__ float g_rs[512];
__device__ __align__(16) __half g_CATh[ROWS_ENC*KPAD]; // row-major: comb(68)|Q1(68)|Q2(68)|pad0
__device__ __align__(16) float g_H[ROWS_ENC*64];
__device__ __align__(16) float g_Hdec[ROWS_DEC*64];
__device__ __align__(16) float g_z[ROWS_ENC*64];
__device__ __align__(16) float g_xt_enc[6*ROWS_ENC*4];
__device__ __align__(16) float g_xt_dec[ROWS_DEC*4];
__device__ float g_tod[64*12];
__device__ __align__(16) __half g_Wzrh[3][KPAD*128];  // [k][g], rows 204..223 zero
__device__ float g_bzr[3][128];
__device__ __align__(16) __half g_Wch[3][KPAD*64];    // [k][c], rows 204..223 zero
__device__ float g_bc[3][64];
__device__ __align__(16) float g_Wmix[128*64];
__device__ float g_bmix[64];

// ---------------- helpers ----------------
__device__ __forceinline__ void mma_f16(float* d, const uint32_t* a, const uint32_t* b) {
    asm volatile(
        "mma.sync.aligned.m16n8k16.row.col.f32.f16.f16.f32 "
        "{%0,%1,%2,%3}, {%4,%5,%6,%7}, {%8,%9}, {%0,%1,%2,%3};"
        : "+f"(d[0]), "+f"(d[1]), "+f"(d[2]), "+f"(d[3])
        : "r"(a[0]), "r"(a[1]), "r"(a[2]), "r"(a[3]), "r"(b[0]), "r"(b[1]));
}
__device__ __forceinline__ float sigm(float x) { return 1.f / (1.f + __expf(-x)); }
__device__ __forceinline__ uint32_t s2u(const void* p) {
    return (uint32_t)__cvta_generic_to_shared(p);
}
__device__ __forceinline__ void ldsm4(uint32_t* r, uint32_t a) {
    asm volatile("ldmatrix.sync.aligned.m8n8.x4.shared.b16 {%0,%1,%2,%3}, [%4];"
        : "=r"(r[0]), "=r"(r[1]), "=r"(r[2]), "=r"(r[3]) : "r"(a));
}

// ---------------- prep ----------------
__global__ void k_rowsum(const float* __restrict__ A) {
    int v = blockIdx.x;
    float s = 0.f;
    for (int w = threadIdx.x; w < 512; w += 128) s += A[v*512+w];
    __shared__ float sh[128];
    sh[threadIdx.x] = s; __syncthreads();
    for (int o = 64; o > 0; o >>= 1) {
        if (threadIdx.x < o) sh[threadIdx.x] += sh[threadIdx.x+o];
        __syncthreads();
    }
    if (threadIdx.x == 0) g_rs[v] = sh[0] + 1.0f;
}

__global__ void k_P(const float* __restrict__ A) {
    int idx = blockIdx.x*blockDim.x + threadIdx.x;
    if (idx >= 512*512) return;
    int w = idx >> 9, v = idx & 511;
    float a  = A[v*512+w];
    float an = (a + (v==w ? 1.f : 0.f)) / g_rs[v];
    float p  = 0.95f*an + 0.95f*a;
    g_P[w*512+v]   = p;
    g_MMh[w*512+v] = __float2half_rn((v==w ? 0.05f : 0.f) + p);   // M1
}

__global__ void k_M2() {
    int idx = blockIdx.x*blockDim.x + threadIdx.x;
    if (idx >= 512*512) return;
    int w = idx >> 9, v = idx & 511;
    const float* pw = g_P + w*512;
    float s = 0.f;
    #pragma unroll 8
    for (int u = 0; u < 512; u++) s += pw[u] * g_P[u*512+v];
    g_MMh[(512+w)*512+v] = __float2half_rn((w==v ? 0.05f : 0.f) + 0.05f*g_P[w*512+v] + s); // M2
}

__global__ void k_weights(const float* __restrict__ Wg, const float* __restrict__ bg) {
    int idx = blockIdx.x*blockDim.x + threadIdx.x;
    const int TZR = 3*204*128, TC = 3*204*64;
    if (idx < TZR) {
        int p = idx / (204*128); int rem = idx % (204*128);
        int k = rem / 128, g = rem % 128;
        int gate = (g < 64) ? 0 : 2;  int c = g & 63;
        int w1 = 6*p + gate;
        g_Wzrh[p][k*128+g] = __float2half_rn(Wg[(w1*204+k)*64+c] + Wg[((w1+1)*204+k)*64+c]);
    } else if (idx < TZR + TC) {
        int j = idx - TZR;
        int p = j / (204*64); int rem = j % (204*64);
        int k = rem / 64, c = rem % 64;
        int w1 = 6*p + 4;
        g_Wch[p][k*64+c] = __float2half_rn(Wg[(w1*204+k)*64+c] + Wg[((w1+1)*204+k)*64+c]);
    } else if (idx < TZR + TC + 3*128) {
        int j = idx - TZR - TC;
        int p = j / 128, g = j % 128;
        int gate = (g < 64) ? 0 : 2; int c = g & 63;
        g_bzr[p][g] = bg[(6*p+gate)*64+c] + bg[(6*p+gate+1)*64+c];
    } else if (idx < TZR + TC + 3*128 + 3*64) {
        int j = idx - TZR - TC - 3*128;
        int p = j / 64, c = j % 64;
        g_bc[p][c] = bg[(6*p+4)*64+c] + bg[(6*p+5)*64+c];
    }
}

__global__ void k_mixw(const float* __restrict__ Wi, const float* __restrict__ bi,
                       const float* __restrict__ Wm, const float* __restrict__ bm) {
    int idx = blockIdx.x*blockDim.x + threadIdx.x;
    if (idx < 4096) {
        int k = idx >> 6, c = idx & 63;
        float s = 0.f;
        for (int j = 0; j < 64; j++) {
            s += Wi[k*64+j]        * Wm[(256+2*j  )*64+c]
               + Wi[4096 + k*64+j] * Wm[(256+2*j+1)*64+c];
        }
        g_Wmix[k*64+c]      = 0.3f*s + 0.7f*Wm[(128+k)*64+c];
        g_Wmix[(64+k)*64+c] = 0.3f*s + 0.7f*Wm[(128+64+k)*64+c];
    } else if (idx < 4096 + 64) {
        int c = idx - 4096;
        float s = 0.f;
        for (int j = 0; j < 64; j++)
            s += 2.f*bi[j]    * Wm[(256+2*j  )*64+c]
               + 2.f*bi[64+j] * Wm[(256+2*j+1)*64+c];
        g_bmix[c] = 0.3f*(s + bm[128+c]) + 0.7f*bm[64+c];
    }
}

__global__ void k_tod(const float* __restrict__ st) {
    int idx = blockIdx.x*blockDim.x + threadIdx.x;
    if (idx >= 64*12) return;
    int b = idx / 12, t = idx % 12;
    g_tod[idx] = (float)(int)((st[(b*5+2)*12+t] + 0.5f) * 6.0f);
}

__global__ void k_xt_enc(const float* __restrict__ x, const float* __restrict__ st) {
    int idx = blockIdx.x*blockDim.x + threadIdx.x;
    if (idx >= 6*ROWS_ENC*4) return;
    int c   = idx & 3;
    int rem = idx >> 2;
    int row = rem & (ROWS_ENC-1);
    int t   = rem >> 16;
    int bp = row >> 9, n = row & 511;
    int b = bp & 63;
    float val;
    if (c < 3) {
        float xe = x[((b*3+c)*512+n)*12 + 2*t];
        float xo = x[((b*3+c)*512+n)*12 + 2*t + 1];
        val = ((bp < 64) ? (xe - xo) : (xe + xo)) * INV_S2;
    } else {
        int s = 2*t;
        float hour   = (st[(b*5+3)*12+s] + 0.5f) * 23.0f;
        float minute = (st[(b*5+4)*12+s] + 0.5f) * 59.0f;
        val = (float)(int)((hour*60.0f + minute) / 5.0f);
    }
    g_xt_enc[idx] = val;
}

// init: H=0, CATh comb for enc t=0 = [xt_enc(0) | 0], xt_dec init
__global__ void k_init_state() {
    int idx = blockIdx.x*blockDim.x + threadIdx.x;
    if (idx < ROWS_ENC*68) {
        int row = idx / 68, c = idx - row*68;
        if (c < 4) {
            g_CATh[(size_t)row*KPAD + c] = __float2half_rn(g_xt_enc[row*4 + c]);
        } else {
            g_CATh[(size_t)row*KPAD + c] = __float2half_rn(0.f);
            g_H[(size_t)row*64 + (c-4)] = 0.f;
        }
        return;
    }
    int j = idx - ROWS_ENC*68;
    if (j < ROWS_DEC*4) {
        int c = j & 3; int row = j >> 2; int b = row >> 9;
        g_xt_dec[j] = (c < 3) ? 0.f : g_tod[b*12 + 0];
    }
}

// ---------------- FP16 diffusion GEMM (ldmatrix, K-tile=32) ----------------
__global__ void __launch_bounds__(256) k_graph_h() {
    const int j0 = blockIdx.x * 128;
    const int m0 = blockIdx.y * 128;
    __shared__ __half As[128][40];
    __shared__ __half Bs[128][40];
    __shared__ int coff[128];
    const int tid = threadIdx.x;
    if (tid < 128) {
        int j = j0 + tid;
        coff[tid] = (j / 68) * BSTRIDE + (j % 68);
    }
    __syncthreads();
    const int lane = tid & 31, wid = tid >> 5;
    const int wm = wid & 1, wn = wid >> 1;        // 2 m-warps x 4 n-warps (64x32)
    const int g = lane >> 2, t4 = lane & 3;
    float C[4][4][4];
    #pragma unroll
    for (int i = 0; i < 4; i++)
        #pragma unroll
        for (int j = 0; j < 4; j++)
            #pragma unroll
            for (int r = 0; r < 4; r++) C[i][j][r] = 0.f;

    const int ar = tid >> 1, ak = (tid & 1) * 16;
    const int bn = tid & 127, bk0 = (tid >> 7) * 16;
    const int cb = coff[bn];

    const int mat = lane >> 3, l7 = lane & 7;
    const int arow_l = (mat & 1)*8 + l7,  acol_l = (mat >> 1)*8;
    const int brow_l = (mat >> 1)*8 + l7, bcol_l = (mat & 1)*8;
    uint32_t a_addr[4], b_addr[2];
    #pragma unroll
    for (int mi = 0; mi < 4; mi++)
        a_addr[mi] = s2u(&As[wm*64 + mi*16 + arow_l][acol_l]);
    #pragma unroll
    for (int pi = 0; pi < 2; pi++)
        b_addr[pi] = s2u(&Bs[wn*32 + pi*16 + brow_l][bcol_l]);

    for (int k0 = 0; k0 < 512; k0 += 32) {
        *(uint4*)&As[ar][ak]     = *(const uint4*)&g_MMh[(size_t)(m0+ar)*512 + k0 + ak];
        *(uint4*)&As[ar][ak + 8] = *(const uint4*)&g_MMh[(size_t)(m0+ar)*512 + k0 + ak + 8];
        #pragma unroll
        for (int i = 0; i < 16; i++)
            Bs[bn][bk0+i] = g_CATh[(size_t)cb + (size_t)(k0+bk0+i)*KPAD];
        __syncthreads();
        #pragma unroll
        for (int kc = 0; kc < 2; kc++) {
            uint32_t a[4][4], bq[2][4];
            #pragma unroll
            for (int mi = 0; mi < 4; mi++) ldsm4(a[mi], a_addr[mi] + kc*32);
            #pragma unroll
            for (int pi = 0; pi < 2; pi++) ldsm4(bq[pi], b_addr[pi] + kc*32);
            #pragma unroll
            for (int mi = 0; mi < 4; mi++)
                #pragma unroll
                for (int ni = 0; ni < 4; ni++)
                    mma_f16(C[mi][ni], a[mi], &bq[ni>>1][(ni&1)*2]);
        }
        __syncthreads();
    }
    #pragma unroll
    for (int mi = 0; mi < 4; mi++) {
        #pragma unroll
        for (int rr = 0; rr < 2; rr++) {
            int m = m0 + wm*64 + mi*16 + g + rr*8;
            int node  = m & 511;
            int obase = (m < 512) ? 68 : 136;
            size_t rbase = (size_t)node * KPAD + obase;
            #pragma unroll
            for (int ni = 0; ni < 4; ni++) {
                int n = wn*32 + ni*8 + 2*t4;   // even; pair (n, n+1) same bp
                __half2 hv = __halves2half2(__float2half_rn(C[mi][ni][rr*2+0]),
                                            __float2half_rn(C[mi][ni][rr*2+1]));
                *(__half2*)&g_CATh[coff[n] + rbase] = hv;
            }
        }
    }
}

// ---------------- FP16 zr gate GEMM + fused temp write (ldmatrix, K-tile=32) ----------------
__global__ void __launch_bounds__(256) k_gatezr_h(int pfix) {
    const int r0 = blockIdx.x * 128;
    const int dec = (pfix == 2);
    const int p = (pfix >= 0) ? pfix : ((r0 < ROWS_DEC) ? 0 : 1);
    const float* H = dec ? g_Hdec : g_H;
    __shared__ __half As[128][40];
    __shared__ __half Bs[128][40];
    const int tid = threadIdx.x;
    const int lane = tid & 31, wid = tid >> 5;
    const int wm = wid & 1, wn = wid >> 1;
    const int g = lane >> 2, t4 = lane & 3;
    float C[4][4][4];
    #pragma unroll
    for (int i = 0; i < 4; i++)
        #pragma unroll
        for (int j = 0; j < 4; j++)
            #pragma unroll
            for (int r = 0; r < 4; r++) C[i][j][r] = 0.f;

    const int ar = tid >> 1, ak = (tid & 1) * 16;
    const int bn = tid & 127, bk0 = (tid >> 7) * 16;
    const __half* Wp = g_Wzrh[p];

    const int mat = lane >> 3, l7 = lane & 7;
    const int arow_l = (mat & 1)*8 + l7,  acol_l = (mat >> 1)*8;
    const int brow_l = (mat >> 1)*8 + l7, bcol_l = (mat & 1)*8;
    uint32_t a_addr[4], b_addr[2];
    #pragma unroll
    for (int mi = 0; mi < 4; mi++)
        a_addr[mi] = s2u(&As[wm*64 + mi*16 + arow_l][acol_l]);
    #pragma unroll
    for (int pi = 0; pi < 2; pi++)
        b_addr[pi] = s2u(&Bs[wn*32 + pi*16 + brow_l][bcol_l]);

    for (int k0 = 0; k0 < KPAD; k0 += 32) {
        *(uint4*)&As[ar][ak]     = *(const uint4*)&g_CATh[(size_t)(r0+ar)*KPAD + k0 + ak];
        *(uint4*)&As[ar][ak + 8] = *(const uint4*)&g_CATh[(size_t)(r0+ar)*KPAD + k0 + ak + 8];
        #pragma unroll
        for (int i = 0; i < 16; i++)
            Bs[bn][bk0+i] = Wp[(k0+bk0+i)*128 + bn];
        __syncthreads();
        #pragma unroll
        for (int kc = 0; kc < 2; kc++) {
            uint32_t a[4][4], bq[2][4];
            #pragma unroll
            for (int mi = 0; mi < 4; mi++) ldsm4(a[mi], a_addr[mi] + kc*32);
            #pragma unroll
            for (int pi = 0; pi < 2; pi++) ldsm4(bq[pi], b_addr[pi] + kc*32);
            #pragma unroll
            for (int mi = 0; mi < 4; mi++)
                #pragma unroll
                for (int ni = 0; ni < 4; ni++)
                    mma_f16(C[mi][ni], a[mi], &bq[ni>>1][(ni&1)*2]);
        }
        __syncthreads();
    }
    #pragma unroll
    for (int mi = 0; mi < 4; mi++) {
        #pragma unroll
        for (int rr = 0; rr < 2; rr++) {
            int row = r0 + wm*64 + mi*16 + g + rr*8;
            #pragma unroll
            for (int ni = 0; ni < 4; ni++) {
                #pragma unroll
                for (int q = 0; q < 2; q++) {
                    int col = wn*32 + ni*8 + 2*t4 + q;
                    float v = sigm(C[mi][ni][rr*2+q] + g_bzr[p][col]);
                    if (col < 64) {
                        g_z[(size_t)row*64 + col] = v;
                    } else {
                        int c = col - 64;
                        float h = H[(size_t)row*64 + c];
                        g_CATh[(size_t)row*KPAD + 4 + c] = __float2half_rn(v*h);
                    }
                }
            }
        }
    }
}

// ---------------- FP16 C gate GEMM + H update + fused comb/xt write (ldmatrix, K-tile=32) ----------------
__global__ void __launch_bounds__(256) k_gatec_h(int pfix, int dec, const float* __restrict__ xt_next) {
    const int r0 = blockIdx.x * 128;
    const int p = (pfix >= 0) ? pfix : ((r0 < ROWS_DEC) ? 0 : 1);
    float* H = dec ? g_Hdec : g_H;
    __shared__ __half As[128][40];
    __shared__ __half Bs[64][40];
    const int tid = threadIdx.x;
    const int lane = tid & 31, wid = tid >> 5;
    const int wm = wid & 3, wn = wid >> 2;
    const int g = lane >> 2, t4 = lane & 3;
    float C[2][4][4];
    #pragma unroll
    for (int i = 0; i < 2; i++)
        #pragma unroll
        for (int j = 0; j < 4; j++)
            #pragma unroll
            for (int r = 0; r < 4; r++) C[i][j][r] = 0.f;

    const int ar = tid >> 1, ak = (tid & 1) * 16;
    const int bn = tid & 63, bk0 = (tid >> 6) * 8;
    const __half* Wp = g_Wch[p];

    const int mat = lane >> 3, l7 = lane & 7;
    const int arow_l = (mat & 1)*8 + l7,  acol_l = (mat >> 1)*8;
    const int brow_l = (mat >> 1)*8 + l7, bcol_l = (mat & 1)*8;
    uint32_t a_addr[2], b_addr[2];
    #pragma unroll
    for (int mi = 0; mi < 2; mi++)
        a_addr[mi] = s2u(&As[wm*32 + mi*16 + arow_l][acol_l]);
    #pragma unroll
    for (int pi = 0; pi < 2; pi++)
        b_addr[pi] = s2u(&Bs[wn*32 + pi*16 + brow_l][bcol_l]);

    for (int k0 = 0; k0 < KPAD; k0 += 32) {
        *(uint4*)&As[ar][ak]     = *(const uint4*)&g_CATh[(size_t)(r0+ar)*KPAD + k0 + ak];
        *(uint4*)&As[ar][ak + 8] = *(const uint4*)&g_CATh[(size_t)(r0+ar)*KPAD + k0 + ak + 8];
        #pragma unroll
        for (int i = 0; i < 8; i++)
            Bs[bn][bk0+i] = Wp[(k0+bk0+i)*64 + bn];
        __syncthreads();
        #pragma unroll
        for (int kc = 0; kc < 2; kc++) {
            uint32_t a[2][4], bq[2][4];
            #pragma unroll
            for (int mi = 0; mi < 2; mi++) ldsm4(a[mi], a_addr[mi] + kc*32);
            #pragma unroll
            for (int pi = 0; pi < 2; pi++) ldsm4(bq[pi], b_addr[pi] + kc*32);
            #pragma unroll
            for (int mi = 0; mi < 2; mi++)
                #pragma unroll
                for (int ni = 0; ni < 4; ni++)
                    mma_f16(C[mi][ni], a[mi], &bq[ni>>1][(ni&1)*2]);
        }
        __syncthreads();
    }
    #pragma unroll
    for (int mi = 0; mi < 2; mi++) {
        #pragma unroll
        for (int rr = 0; rr < 2; rr++) {
            int row = r0 + wm*32 + mi*16 + g + rr*8;
            #pragma unroll
            for (int ni = 0; ni < 4; ni++) {
                #pragma unroll
                for (int q = 0; q < 2; q++) {
                    int col = wn*32 + ni*8 + 2*t4 + q;
                    float c = tanhf(C[mi][ni][rr*2+q] + g_bc[p][col]);
                    float z = g_z[(size_t)row*64 + col];
                    float h = H[(size_t)row*64 + col];
                    float hn = z*h + (1.f - z)*c;
                    H[(size_t)row*64 + col] = hn;
                    g_CATh[(size_t)row*KPAD + 4 + col] = __float2half_rn(hn);
                    if (xt_next != nullptr && col < 4)
                        g_CATh[(size_t)row*KPAD + col] =
                            __float2half_rn(xt_next[(size_t)row*4 + col]);
                }
            }
        }
    }
}

// ---------------- mix GEMM + fused comb write for decoder step 0 ----------------
__global__ void __launch_bounds__(256) k_mix() {
    const int r0 = blockIdx.x * 128;
    __shared__ float As[8][128];
    __shared__ float Bs[8][64];
    const int tid = threadIdx.x;
    float acc[8][4];
    #pragma unroll
    for (int i = 0; i < 8; i++)
        #pragma unroll
        for (int j = 0; j < 4; j++) acc[i][j] = 0.f;

    const int arow = tid >> 1, acol = (tid & 1) * 4;
    const int tx = tid & 15, ty = tid >> 4;

    for (int k0 = 0; k0 < 128; k0 += 8) {
        int row = r0 + arow;
        const float* src = (k0 < 64) ? &g_H[(size_t)row*64 + k0 + acol]
                                     : &g_H[((size_t)row + ROWS_DEC)*64 + (k0 - 64) + acol];
        float4 av = *(const float4*)src;
        As[acol+0][arow] = av.x; As[acol+1][arow] = av.y;
        As[acol+2][arow] = av.z; As[acol+3][arow] = av.w;
        #pragma unroll
        for (int r = 0; r < 2; r++) {
            int ii = tid + r*256;
            int k = ii >> 6, j = ii & 63;
            Bs[k][j] = g_Wmix[(k0+k)*64 + j];
        }
        __syncthreads();
        #pragma unroll
        for (int kk = 0; kk < 8; kk++) {
            float4 a0 = *(const float4*)&As[kk][ty*8];
            float4 a1 = *(const float4*)&As[kk][ty*8+4];
            float4 b0 = *(const float4*)&Bs[kk][tx*4];
            float aa[8] = {a0.x,a0.y,a0.z,a0.w,a1.x,a1.y,a1.z,a1.w};
            float bb[4] = {b0.x,b0.y,b0.z,b0.w};
            #pragma unroll
            for (int i = 0; i < 8; i++)
                #pragma unroll
                for (int j = 0; j < 4; j++)
                    acc[i][j] += aa[i]*bb[j];
        }
        __syncthreads();
    }
    #pragma unroll
    for (int i = 0; i < 8; i++) {
        int row = r0 + ty*8 + i;
        #pragma unroll
        for (int j = 0; j < 4; j++) {
            int col = tx*4 + j;
            float hv = acc[i][j] + g_bmix[col];
            g_Hdec[(size_t)row*64 + col] = hv;
            g_CATh[(size_t)row*KPAD + 4 + col] = __float2half_rn(hv);
            if (col < 4)
                g_CATh[(size_t)row*KPAD + col] =
                    __float2half_rn(g_xt_dec[(size_t)row*4 + col]);
        }
    }
}

// ---------------- decoder FC + output scatter + fused next-xt comb write ----------------
__global__ void k_fc(const float* __restrict__ Wfc, const float* __restrict__ bfc,
                     float* __restrict__ out, int t) {
    int row = blockIdx.x*blockDim.x + threadIdx.x;
    if (row >= ROWS_DEC) return;
    int b = row >> 9, n = row & 511;
    float a0 = bfc[0], a1 = bfc[1], a2 = bfc[2];
    const float* h = &g_Hdec[(size_t)row*64];
    #pragma unroll 8
    for (int k = 0; k < 64; k++) {
        float hv = h[k];
        a0 += hv * Wfc[k*3+0];
        a1 += hv * Wfc[k*3+1];
        a2 += hv * Wfc[k*3+2];
    }
    float av[3] = {a0, a1, a2};
    #pragma unroll
    for (int d = 0; d < 3; d++) {
        int L = 3*t + d;
        int dp = L / 12, tp = L % 12;
        out[((b*3+dp)*512 + n)*12 + tp] = av[d];
        g_CATh[(size_t)row*KPAD + d] = __float2half_rn(av[d]);
    }
    if (t + 1 < 12)
        g_CATh[(size_t)row*KPAD + 3] = __float2half_rn(g_tod[b*12 + t + 1]);
}

// ---------------- launch ----------------
extern "C" void kernel_launch(void* const* d_in, const int* in_sizes, int n_in,
                              void* d_out, int out_size) {
    const float* x   = (const float*)d_in[0];
    const float* st  = (const float*)d_in[2];
    const float* A   = (const float*)d_in[3];
    const float* Wg  = (const float*)d_in[4];
    const float* bg  = (const float*)d_in[5];
    const float* Wm  = (const float*)d_in[6];
    const float* bm  = (const float*)d_in[7];
    const float* Wi  = (const float*)d_in[8];
    const float* bi  = (const float*)d_in[9];
    const float* Wfc = (const float*)d_in[10];
    const float* bfc = (const float*)d_in[11];
    float* out = (float*)d_out;

    static float* xt_enc_base = nullptr;
    if (!xt_enc_base) cudaGetSymbolAddress((void**)&xt_enc_base, g_xt_enc);

    // prep
    k_rowsum<<<512, 128>>>(A);
    k_P<<<1024, 256>>>(A);
    k_M2<<<1024, 256>>>();
    k_weights<<<(3*204*128 + 3*204*64 + 3*128 + 3*64 + 255)/256, 256>>>(Wg, bg);
    k_mixw<<<(4160 + 255)/256, 256>>>(Wi, bi, Wm, bm);
    k_tod<<<3, 256>>>(st);
    k_xt_enc<<<(6*ROWS_ENC*4)/256, 256>>>(x, st);
    k_init_state<<<((size_t)ROWS_ENC*68 + ROWS_DEC*4 + 255)/256, 256>>>();

    // encoders (D + A batched: 128 batch-slices)
    for (int t = 0; t < 6; t++) {
        k_graph_h<<<dim3(68, 8), 256>>>();
        k_gatezr_h<<<ROWS_ENC/128, 256>>>(-1);
        k_graph_h<<<dim3(68, 8), 256>>>();
        const float* xtn = (t < 5) ? (xt_enc_base + (size_t)(t+1)*ROWS_ENC*4) : nullptr;
        k_gatec_h<<<ROWS_ENC/128, 256>>>(-1, 0, xtn);
    }

    // mix -> decoder initial H + comb
    k_mix<<<ROWS_DEC/128, 256>>>();

    // decoder
    for (int t = 0; t < 12; t++) {
        k_graph_h<<<dim3(34, 8), 256>>>();
        k_gatezr_h<<<ROWS_DEC/128, 256>>>(2);
        k_graph_h<<<dim3(34, 8), 256>>>();
        k_gatec_h<<<ROWS_DEC/128, 256>>>(2, 1, nullptr);
        k_fc<<<ROWS_DEC/256, 256>>>(Wfc, bfc, out, t);
    }
}